// round 15
// baseline (speedup 1.0000x reference)
#include <cuda_runtime.h>
#include <cuda_fp16.h>
#include <cstdint>
#include <math.h>

// ---------------------------------------------------------------------------
// Problem dims
// ---------------------------------------------------------------------------
constexpr int M_DIM = 8192;
constexpr int N_DIM = 4096;
constexpr int K_DIM = 4096;
constexpr int GROUPS = K_DIM / 32;
constexpr int PLANE_STRIDE = N_DIM * GROUPS;

// Scratch (static device arrays = allowed). fp16 operands.
__device__ __half g_xh[(size_t)M_DIM * K_DIM];   // 67 MB
__device__ __half g_wh[(size_t)N_DIM * K_DIM];   // 33 MB

// ---------------------------------------------------------------------------
// Helpers (base ISA only — compute_103-safe)
// ---------------------------------------------------------------------------
__device__ __forceinline__ uint32_t smem_to_u32(const void* p) {
    uint32_t a;
    asm("{ .reg .u64 t; cvta.to.shared.u64 t, %1; cvt.u32.u64 %0, t; }"
        : "=r"(a) : "l"(p));
    return a;
}

#define CP_ASYNC16(dst, src) \
    asm volatile("cp.async.cg.shared.global [%0], [%1], 16;" :: "r"(dst), "l"(src) : "memory")
#define CP_COMMIT() asm volatile("cp.async.commit_group;" ::: "memory")
#define CP_WAIT0()  asm volatile("cp.async.wait_group 0;" ::: "memory")

__device__ __forceinline__ void mma_f16(float* d, const uint32_t* a, const uint32_t* b) {
    asm volatile(
        "mma.sync.aligned.m16n8k16.row.col.f32.f16.f16.f32 "
        "{%0,%1,%2,%3}, {%4,%5,%6,%7}, {%8,%9}, {%0,%1,%2,%3};"
        : "+f"(d[0]), "+f"(d[1]), "+f"(d[2]), "+f"(d[3])
        : "r"(a[0]), "r"(a[1]), "r"(a[2]), "r"(a[3]), "r"(b[0]), "r"(b[1]));
}

// ---------------------------------------------------------------------------
// Kernel 1 (fused preproc) — unchanged from R14 (combined smem LUT dequant).
// ---------------------------------------------------------------------------
constexpr int DQ_BLOCKS = (N_DIM * GROUPS) / 256;                    // 2048
constexpr int CV_BLOCKS = (int)(((size_t)M_DIM * K_DIM / 8) / 256);  // 16384

__global__ __launch_bounds__(256) void preproc(
    const int* __restrict__ qw, const float* __restrict__ lut4,
    const float* __restrict__ lut5, const float* __restrict__ zp,
    const float* __restrict__ x)
{
    if (blockIdx.x < DQ_BLOCKS) {
        __shared__ float L[2][32];               // 2 output rows per block
        const int tid = threadIdx.x;
        const int idx = blockIdx.x * 256 + tid;
        const int g = idx & (GROUPS - 1);
        const int o = idx >> 7;

        float z = zp[0];
        float r = 2.0f - 3.0f / (1.0f + expf(-z));   // 2 - 3*sigmoid(z)
        float s = 1.0f - r;

        if (tid < 64) {
            int row = tid >> 5, c5 = tid & 31;
            int oo = blockIdx.x * 2 + row;
            L[row][c5] = r * lut4[oo * 16 + (c5 >> 1)] + s * lut5[oo * 32 + c5];
        }

        int base = o * GROUPS + g;
        unsigned q0 = (unsigned)qw[base];
        unsigned q1 = (unsigned)qw[base + PLANE_STRIDE];
        unsigned q2 = (unsigned)qw[base + 2 * PLANE_STRIDE];
        unsigned q3 = (unsigned)qw[base + 3 * PLANE_STRIDE];
        unsigned q4 = (unsigned)qw[base + 4 * PLANE_STRIDE];

        __syncthreads();
        const float* Lr = L[tid >> 7];

        __align__(16) __half vals[32];
#pragma unroll
        for (int b = 0; b < 32; b++) {
            unsigned c5 = (((q0 >> b) & 1u) << 4) | (((q1 >> b) & 1u) << 3)
                        | (((q2 >> b) & 1u) << 2) | (((q3 >> b) & 1u) << 1)
                        |  ((q4 >> b) & 1u);
            vals[b] = __float2half_rn(Lr[c5]);
        }
        __half* dst = g_wh + (size_t)o * K_DIM + g * 32;
        const uint4* sv = reinterpret_cast<const uint4*>(vals);
#pragma unroll
        for (int i = 0; i < 4; i++)
            reinterpret_cast<uint4*>(dst)[i] = sv[i];
    } else {
        size_t i = ((size_t)(blockIdx.x - DQ_BLOCKS) * 256 + threadIdx.x) * 8;
        float4 a = *reinterpret_cast<const float4*>(x + i);
        float4 b = *reinterpret_cast<const float4*>(x + i + 4);
        __align__(16) __half h[8];
        h[0] = __float2half_rn(a.x); h[1] = __float2half_rn(a.y);
        h[2] = __float2half_rn(a.z); h[3] = __float2half_rn(a.w);
        h[4] = __float2half_rn(b.x); h[5] = __float2half_rn(b.y);
        h[6] = __float2half_rn(b.z); h[7] = __float2half_rn(b.w);
        *reinterpret_cast<uint4*>(g_xh + i) = *reinterpret_cast<const uint4*>(h);
    }
}

// ---------------------------------------------------------------------------
// Kernel 2: hybrid HMMA + FFMA GEMM.  out = xh @ wh^T + bias
// Tensor path (m16n8k16, at its rt~12 issue ceiling) covers k[0, 3840)
// in 30 BK=128 chunks; the idle FMA pipe computes k[3840, 4096) as
// fp32 scalar FFMAs into the SAME accumulators, spread across the 30
// chunks (5 half2-pairs/chunk for c<8, else 4; 128 pairs total).
// ---------------------------------------------------------------------------
constexpr int BM = 256, BN = 128, BK = 128;
constexpr int PITCH = 136;                      // halves per smem row
constexpr int ROWS = BM + BN;                   // 384
constexpr int STAGE_HALVES = ROWS * PITCH;      // 52224
constexpr int K_TENSOR = 3840;                  // 30 chunks
constexpr int NCHUNK_T = K_TENSOR / BK;         // 30
constexpr int SMEM_BYTES = 2 * STAGE_HALVES * 2;  // 208896

__global__ __launch_bounds__(256, 1) void gemm_f16(
    const float* __restrict__ bias, float* __restrict__ out)
{
    extern __shared__ __half sm[];
    const int tid = threadIdx.x;
    const int lane = tid & 31, wid = tid >> 5;
    const int wm = wid >> 1, wn = wid & 1;       // warp grid 4x2
    const int grp = lane >> 2, qid = lane & 3;
    const int mBase = blockIdx.y * BM;
    const int nBase = blockIdx.x * BN;

    const __half* Ag = g_xh + (size_t)mBase * K_DIM;
    const __half* Bg = g_wh + (size_t)nBase * K_DIM;
    const uint32_t smAddr = smem_to_u32(sm);

    // cp.async mapping (unchanged)
    const int rbase = tid >> 4;
    const int seg = tid & 15;
    const char* srcA = (const char*)(Ag + (size_t)rbase * K_DIM + seg * 8);
    const char* srcB = (const char*)(Bg + (size_t)rbase * K_DIM + seg * 8);
    const uint32_t dst0 = (uint32_t)((rbase * PITCH + seg * 8) * 2);
    constexpr size_t SRC_IT = (size_t)16 * K_DIM * 2;
    constexpr uint32_t DST_IT = 16 * PITCH * 2;

    // FFMA-path base pointers (k = K_TENSOR onward)
    const __half* aF = g_xh + (size_t)(mBase + wm * 64 + grp) * K_DIM + K_TENSOR;
    const __half* bF = g_wh + (size_t)(nBase + wn * 64 + 2 * qid) * K_DIM + K_TENSOR;

    float acc[4][8][4];
#pragma unroll
    for (int i = 0; i < 4; i++)
#pragma unroll
        for (int j = 0; j < 8; j++)
#pragma unroll
            for (int t = 0; t < 4; t++) acc[i][j][t] = 0.0f;

    auto load_chunk = [&](int c) {
        uint32_t stAddr = smAddr + (uint32_t)((c & 1) * STAGE_HALVES * 2) + dst0;
        size_t goff = (size_t)c * (BK * 2);
        const char* sA = srcA + goff;
        const char* sB = srcB + goff;
#pragma unroll
        for (int it = 0; it < 16; it++)          // A rows 0..255
            CP_ASYNC16(stAddr + it * DST_IT, sA + it * SRC_IT);
        uint32_t stB = stAddr + 16 * DST_IT;
#pragma unroll
        for (int it = 0; it < 8; it++)           // B rows 256..383
            CP_ASYNC16(stB + it * DST_IT, sB + it * SRC_IT);
    };

    load_chunk(0); CP_COMMIT();

    for (int c = 0; c < NCHUNK_T; c++) {
        CP_WAIT0();
        __syncthreads();

        if (c + 1 < NCHUNK_T) { load_chunk(c + 1); CP_COMMIT(); }

        const __half* st = sm + (c & 1) * STAGE_HALVES;
#pragma unroll
        for (int ks = 0; ks < 8; ks++) {
            const int k0 = ks * 16;
            uint32_t a[4][4], b[8][2];
#pragma unroll
            for (int mt = 0; mt < 4; mt++) {
                int m = wm * 64 + mt * 16 + grp;
                const __half* p = st + m * PITCH + k0 + 2 * qid;
                a[mt][0] = *reinterpret_cast<const uint32_t*>(p);
                a[mt][1] = *reinterpret_cast<const uint32_t*>(p + 8 * PITCH);
                a[mt][2] = *reinterpret_cast<const uint32_t*>(p + 8);
                a[mt][3] = *reinterpret_cast<const uint32_t*>(p + 8 * PITCH + 8);
            }
#pragma unroll
            for (int nt = 0; nt < 8; nt++) {
                int n = wn * 64 + nt * 8 + grp;
                const __half* p = st + (BM + n) * PITCH + k0 + 2 * qid;
                b[nt][0] = *reinterpret_cast<const uint32_t*>(p);
                b[nt][1] = *reinterpret_cast<const uint32_t*>(p + 8);
            }
#pragma unroll
            for (int mt = 0; mt < 4; mt++)
#pragma unroll
                for (int nt = 0; nt < 8; nt++)
                    mma_f16(acc[mt][nt], a[mt], b[nt]);
        }

        // FFMA quantum: 5 k-pairs for c<8 else 4 (total 128 pairs = 256 k).
        {
            const int np = (c < 8) ? 5 : 4;
            const int kp0 = (c < 8) ? 5 * c : 40 + 4 * (c - 8);
#pragma unroll
            for (int j = 0; j < 5; j++) {
                if (j < np) {
                    const int kp = kp0 + j;        // k-pair index; k = 2*kp
                    float2 av[4][2];
#pragma unroll
                    for (int mt = 0; mt < 4; mt++)
#pragma unroll
                        for (int h = 0; h < 2; h++)
                            av[mt][h] = __half22float2(
                                *reinterpret_cast<const __half2*>(
                                    aF + (size_t)(mt * 16 + h * 8) * K_DIM + 2 * kp));
                    float2 bv[8][2];
#pragma unroll
                    for (int nt = 0; nt < 8; nt++)
#pragma unroll
                        for (int jj = 0; jj < 2; jj++)
                            bv[nt][jj] = __half22float2(
                                *reinterpret_cast<const __half2*>(
                                    bF + (size_t)(nt * 8 + jj) * K_DIM + 2 * kp));
#pragma unroll
                    for (int mt = 0; mt < 4; mt++)
#pragma unroll
                        for (int nt = 0; nt < 8; nt++) {
                            acc[mt][nt][0] = fmaf(av[mt][0].x, bv[nt][0].x,
                                             fmaf(av[mt][0].y, bv[nt][0].y, acc[mt][nt][0]));
                            acc[mt][nt][1] = fmaf(av[mt][0].x, bv[nt][1].x,
                                             fmaf(av[mt][0].y, bv[nt][1].y, acc[mt][nt][1]));
                            acc[mt][nt][2] = fmaf(av[mt][1].x, bv[nt][0].x,
                                             fmaf(av[mt][1].y, bv[nt][0].y, acc[mt][nt][2]));
                            acc[mt][nt][3] = fmaf(av[mt][1].x, bv[nt][1].x,
                                             fmaf(av[mt][1].y, bv[nt][1].y, acc[mt][nt][3]));
                        }
                }
            }
        }
    }

    // -- epilogue: bias + float2 stores --
#pragma unroll
    for (int mt = 0; mt < 4; mt++) {
        int m0 = mBase + wm * 64 + mt * 16 + grp;
#pragma unroll
        for (int nt = 0; nt < 8; nt++) {
            int n0 = nBase + wn * 64 + nt * 8 + 2 * qid;
            float2 bv = *reinterpret_cast<const float2*>(bias + n0);
            float2 v0 = make_float2(acc[mt][nt][0] + bv.x, acc[mt][nt][1] + bv.y);
            float2 v1 = make_float2(acc[mt][nt][2] + bv.x, acc[mt][nt][3] + bv.y);
            *reinterpret_cast<float2*>(out + (size_t)m0 * N_DIM + n0) = v0;
            *reinterpret_cast<float2*>(out + (size_t)(m0 + 8) * N_DIM + n0) = v1;
        }
    }
}

// ---------------------------------------------------------------------------
// Launch: inputs: x, z, lut4, lut5, bias, qweight
// ---------------------------------------------------------------------------
extern "C" void kernel_launch(void* const* d_in, const int* in_sizes, int n_in,
                              void* d_out, int out_size)
{
    const float* x    = (const float*)d_in[0];
    const float* z    = (const float*)d_in[1];
    const float* lut4 = (const float*)d_in[2];
    const float* lut5 = (const float*)d_in[3];
    const float* bias = (const float*)d_in[4];
    const int* qweight = (const int*)d_in[5];
    float* out = (float*)d_out;
    (void)in_sizes; (void)n_in; (void)out_size;

    cudaFuncSetAttribute(gemm_f16, cudaFuncAttributeMaxDynamicSharedMemorySize, SMEM_BYTES);

    preproc<<<DQ_BLOCKS + CV_BLOCKS, 256>>>(qweight, lut4, lut5, z, x);

    dim3 grid(N_DIM / BN, M_DIM / BM);   // (32, 32)
    gemm_f16<<<grid, 256, SMEM_BYTES>>>(bias, out);
}

// round 16
// speedup vs baseline: 1.6927x; 1.6927x over previous
#include <cuda_runtime.h>
#include <cuda_fp16.h>
#include <cstdint>
#include <math.h>

// ---------------------------------------------------------------------------
// Problem dims
// ---------------------------------------------------------------------------
constexpr int M_DIM = 8192;
constexpr int N_DIM = 4096;
constexpr int K_DIM = 4096;
constexpr int GROUPS = K_DIM / 32;
constexpr int PLANE_STRIDE = N_DIM * GROUPS;

// Scratch (static device arrays = allowed). fp16 operands.
__device__ __half g_xh[(size_t)M_DIM * K_DIM];   // 67 MB
__device__ __half g_wh[(size_t)N_DIM * K_DIM];   // 33 MB

// ---------------------------------------------------------------------------
// Helpers (base ISA only — compute_103-safe)
// ---------------------------------------------------------------------------
__device__ __forceinline__ uint32_t smem_to_u32(const void* p) {
    uint32_t a;
    asm("{ .reg .u64 t; cvta.to.shared.u64 t, %1; cvt.u32.u64 %0, t; }"
        : "=r"(a) : "l"(p));
    return a;
}

#define CP_ASYNC16(dst, src) \
    asm volatile("cp.async.cg.shared.global [%0], [%1], 16;" :: "r"(dst), "l"(src) : "memory")
#define CP_COMMIT() asm volatile("cp.async.commit_group;" ::: "memory")
#define CP_WAIT0()  asm volatile("cp.async.wait_group 0;" ::: "memory")

__device__ __forceinline__ void mma_f16(float* d, const uint32_t* a, const uint32_t* b) {
    asm volatile(
        "mma.sync.aligned.m16n8k16.row.col.f32.f16.f16.f32 "
        "{%0,%1,%2,%3}, {%4,%5,%6,%7}, {%8,%9}, {%0,%1,%2,%3};"
        : "+f"(d[0]), "+f"(d[1]), "+f"(d[2]), "+f"(d[3])
        : "r"(a[0]), "r"(a[1]), "r"(a[2]), "r"(a[3]), "r"(b[0]), "r"(b[1]));
}

// Streaming store: output is written once and never re-read by this launch;
// .cs keeps it from displacing B-tiles in L2.
__device__ __forceinline__ void stg_cs_f2(float* p, float2 v) {
    asm volatile("st.global.cs.v2.f32 [%0], {%1, %2};"
                 :: "l"(p), "f"(v.x), "f"(v.y) : "memory");
}

// ---------------------------------------------------------------------------
// Kernel 1 (fused preproc):
//   blocks [0, 2048):      dequant + blend -> W fp16 (combined smem LUT)
//   blocks [2048, 18432):  x -> fp16
// ---------------------------------------------------------------------------
constexpr int DQ_BLOCKS = (N_DIM * GROUPS) / 256;                    // 2048
constexpr int CV_BLOCKS = (int)(((size_t)M_DIM * K_DIM / 8) / 256);  // 16384

__global__ __launch_bounds__(256) void preproc(
    const int* __restrict__ qw, const float* __restrict__ lut4,
    const float* __restrict__ lut5, const float* __restrict__ zp,
    const float* __restrict__ x)
{
    if (blockIdx.x < DQ_BLOCKS) {
        __shared__ float L[2][32];               // 2 output rows per block
        const int tid = threadIdx.x;
        const int idx = blockIdx.x * 256 + tid;
        const int g = idx & (GROUPS - 1);
        const int o = idx >> 7;

        float z = zp[0];
        float r = 2.0f - 3.0f / (1.0f + expf(-z));   // 2 - 3*sigmoid(z)
        float s = 1.0f - r;

        if (tid < 64) {
            int row = tid >> 5, c5 = tid & 31;
            int oo = blockIdx.x * 2 + row;
            L[row][c5] = r * lut4[oo * 16 + (c5 >> 1)] + s * lut5[oo * 32 + c5];
        }

        int base = o * GROUPS + g;
        unsigned q0 = (unsigned)qw[base];
        unsigned q1 = (unsigned)qw[base + PLANE_STRIDE];
        unsigned q2 = (unsigned)qw[base + 2 * PLANE_STRIDE];
        unsigned q3 = (unsigned)qw[base + 3 * PLANE_STRIDE];
        unsigned q4 = (unsigned)qw[base + 4 * PLANE_STRIDE];

        __syncthreads();
        const float* Lr = L[tid >> 7];

        __align__(16) __half vals[32];
#pragma unroll
        for (int b = 0; b < 32; b++) {
            unsigned c5 = (((q0 >> b) & 1u) << 4) | (((q1 >> b) & 1u) << 3)
                        | (((q2 >> b) & 1u) << 2) | (((q3 >> b) & 1u) << 1)
                        |  ((q4 >> b) & 1u);
            vals[b] = __float2half_rn(Lr[c5]);
        }
        __half* dst = g_wh + (size_t)o * K_DIM + g * 32;
        const uint4* sv = reinterpret_cast<const uint4*>(vals);
#pragma unroll
        for (int i = 0; i < 4; i++)
            reinterpret_cast<uint4*>(dst)[i] = sv[i];
    } else {
        size_t i = ((size_t)(blockIdx.x - DQ_BLOCKS) * 256 + threadIdx.x) * 8;
        float4 a = *reinterpret_cast<const float4*>(x + i);
        float4 b = *reinterpret_cast<const float4*>(x + i + 4);
        __align__(16) __half h[8];
        h[0] = __float2half_rn(a.x); h[1] = __float2half_rn(a.y);
        h[2] = __float2half_rn(a.z); h[3] = __float2half_rn(a.w);
        h[4] = __float2half_rn(b.x); h[5] = __float2half_rn(b.y);
        h[6] = __float2half_rn(b.z); h[7] = __float2half_rn(b.w);
        *reinterpret_cast<uint4*>(g_xh + i) = *reinterpret_cast<const uint4*>(h);
    }
}

// ---------------------------------------------------------------------------
// Kernel 2: fp16 mma.sync m16n8k16 GEMM (R14 configuration — measured best).
// CTA 256x128, BK=128, 2-stage cp.async pipeline, 8 warps (4x2), warp 64x64.
// At ~99% of the legacy-HMMA issue-rate ceiling (rt~12/SMSP, confirmed
// invariant across warp-count / ldmatrix / BK / hybrid variants R9-R15).
// ---------------------------------------------------------------------------
constexpr int BM = 256, BN = 128, BK = 128;
constexpr int PITCH = 136;                      // halves per smem row
constexpr int ROWS = BM + BN;                   // 384
constexpr int STAGE_HALVES = ROWS * PITCH;      // 52224
constexpr int NCHUNK = K_DIM / BK;              // 32
constexpr int SMEM_BYTES = 2 * STAGE_HALVES * 2;  // 208896

__global__ __launch_bounds__(256, 1) void gemm_f16(
    const float* __restrict__ bias, float* __restrict__ out)
{
    extern __shared__ __half sm[];
    const int tid = threadIdx.x;
    const int lane = tid & 31, wid = tid >> 5;
    const int wm = wid >> 1, wn = wid & 1;       // warp grid 4x2
    const int grp = lane >> 2, qid = lane & 3;
    const int mBase = blockIdx.y * BM;
    const int nBase = blockIdx.x * BN;

    const __half* Ag = g_xh + (size_t)mBase * K_DIM;
    const __half* Bg = g_wh + (size_t)nBase * K_DIM;
    const uint32_t smAddr = smem_to_u32(sm);

    const int rbase = tid >> 4;
    const int seg = tid & 15;
    const char* srcA = (const char*)(Ag + (size_t)rbase * K_DIM + seg * 8);
    const char* srcB = (const char*)(Bg + (size_t)rbase * K_DIM + seg * 8);
    const uint32_t dst0 = (uint32_t)((rbase * PITCH + seg * 8) * 2);
    constexpr size_t SRC_IT = (size_t)16 * K_DIM * 2;
    constexpr uint32_t DST_IT = 16 * PITCH * 2;

    float acc[4][8][4];
#pragma unroll
    for (int i = 0; i < 4; i++)
#pragma unroll
        for (int j = 0; j < 8; j++)
#pragma unroll
            for (int t = 0; t < 4; t++) acc[i][j][t] = 0.0f;

    auto load_chunk = [&](int c) {
        uint32_t stAddr = smAddr + (uint32_t)((c & 1) * STAGE_HALVES * 2) + dst0;
        size_t goff = (size_t)c * (BK * 2);
        const char* sA = srcA + goff;
        const char* sB = srcB + goff;
#pragma unroll
        for (int it = 0; it < 16; it++)          // A rows 0..255
            CP_ASYNC16(stAddr + it * DST_IT, sA + it * SRC_IT);
        uint32_t stB = stAddr + 16 * DST_IT;
#pragma unroll
        for (int it = 0; it < 8; it++)           // B rows 256..383
            CP_ASYNC16(stB + it * DST_IT, sB + it * SRC_IT);
    };

    load_chunk(0); CP_COMMIT();

    for (int c = 0; c < NCHUNK; c++) {
        CP_WAIT0();
        __syncthreads();

        if (c + 1 < NCHUNK) { load_chunk(c + 1); CP_COMMIT(); }

        const __half* st = sm + (c & 1) * STAGE_HALVES;
#pragma unroll
        for (int ks = 0; ks < 8; ks++) {
            const int k0 = ks * 16;
            uint32_t a[4][4], b[8][2];
#pragma unroll
            for (int mt = 0; mt < 4; mt++) {
                int m = wm * 64 + mt * 16 + grp;
                const __half* p = st + m * PITCH + k0 + 2 * qid;
                a[mt][0] = *reinterpret_cast<const uint32_t*>(p);
                a[mt][1] = *reinterpret_cast<const uint32_t*>(p + 8 * PITCH);
                a[mt][2] = *reinterpret_cast<const uint32_t*>(p + 8);
                a[mt][3] = *reinterpret_cast<const uint32_t*>(p + 8 * PITCH + 8);
            }
#pragma unroll
            for (int nt = 0; nt < 8; nt++) {
                int n = wn * 64 + nt * 8 + grp;
                const __half* p = st + (BM + n) * PITCH + k0 + 2 * qid;
                b[nt][0] = *reinterpret_cast<const uint32_t*>(p);
                b[nt][1] = *reinterpret_cast<const uint32_t*>(p + 8);
            }
#pragma unroll
            for (int mt = 0; mt < 4; mt++)
#pragma unroll
                for (int nt = 0; nt < 8; nt++)
                    mma_f16(acc[mt][nt], a[mt], b[nt]);
        }
    }

    // -- epilogue: bias + streaming float2 stores --
#pragma unroll
    for (int mt = 0; mt < 4; mt++) {
        int m0 = mBase + wm * 64 + mt * 16 + grp;
#pragma unroll
        for (int nt = 0; nt < 8; nt++) {
            int n0 = nBase + wn * 64 + nt * 8 + 2 * qid;
            float2 bv = *reinterpret_cast<const float2*>(bias + n0);
            stg_cs_f2(out + (size_t)m0 * N_DIM + n0,
                      make_float2(acc[mt][nt][0] + bv.x, acc[mt][nt][1] + bv.y));
            stg_cs_f2(out + (size_t)(m0 + 8) * N_DIM + n0,
                      make_float2(acc[mt][nt][2] + bv.x, acc[mt][nt][3] + bv.y));
        }
    }
}

// ---------------------------------------------------------------------------
// Launch: inputs: x, z, lut4, lut5, bias, qweight
// ---------------------------------------------------------------------------
extern "C" void kernel_launch(void* const* d_in, const int* in_sizes, int n_in,
                              void* d_out, int out_size)
{
    const float* x    = (const float*)d_in[0];
    const float* z    = (const float*)d_in[1];
    const float* lut4 = (const float*)d_in[2];
    const float* lut5 = (const float*)d_in[3];
    const float* bias = (const float*)d_in[4];
    const int* qweight = (const int*)d_in[5];
    float* out = (float*)d_out;
    (void)in_sizes; (void)n_in; (void)out_size;

    cudaFuncSetAttribute(gemm_f16, cudaFuncAttributeMaxDynamicSharedMemorySize, SMEM_BYTES);

    preproc<<<DQ_BLOCKS + CV_BLOCKS, 256>>>(qweight, lut4, lut5, z, x);

    dim3 grid(N_DIM / BN, M_DIM / BM);   // (32, 32)
    gemm_f16<<<grid, 256, SMEM_BYTES>>>(bias, out);
}

// round 17
// speedup vs baseline: 1.6952x; 1.0015x over previous
#include <cuda_runtime.h>
#include <cuda_fp16.h>
#include <cstdint>
#include <math.h>

// ---------------------------------------------------------------------------
// Problem dims
// ---------------------------------------------------------------------------
constexpr int M_DIM = 8192;
constexpr int N_DIM = 4096;
constexpr int K_DIM = 4096;
constexpr int GROUPS = K_DIM / 32;
constexpr int PLANE_STRIDE = N_DIM * GROUPS;

// Scratch (static device arrays = allowed). fp16 operands.
__device__ __half g_xh[(size_t)M_DIM * K_DIM];   // 67 MB
__device__ __half g_wh[(size_t)N_DIM * K_DIM];   // 33 MB

// ---------------------------------------------------------------------------
// Helpers (base ISA only — compute_103-safe)
// ---------------------------------------------------------------------------
__device__ __forceinline__ uint32_t smem_to_u32(const void* p) {
    uint32_t a;
    asm("{ .reg .u64 t; cvta.to.shared.u64 t, %1; cvt.u32.u64 %0, t; }"
        : "=r"(a) : "l"(p));
    return a;
}

#define CP_ASYNC16(dst, src) \
    asm volatile("cp.async.cg.shared.global [%0], [%1], 16;" :: "r"(dst), "l"(src) : "memory")
#define CP_COMMIT() asm volatile("cp.async.commit_group;" ::: "memory")
#define CP_WAIT0()  asm volatile("cp.async.wait_group 0;" ::: "memory")

__device__ __forceinline__ void mma_f16(float* d, const uint32_t* a, const uint32_t* b) {
    asm volatile(
        "mma.sync.aligned.m16n8k16.row.col.f32.f16.f16.f32 "
        "{%0,%1,%2,%3}, {%4,%5,%6,%7}, {%8,%9}, {%0,%1,%2,%3};"
        : "+f"(d[0]), "+f"(d[1]), "+f"(d[2]), "+f"(d[3])
        : "r"(a[0]), "r"(a[1]), "r"(a[2]), "r"(a[3]), "r"(b[0]), "r"(b[1]));
}

__device__ __forceinline__ void stg_cs_f2(float* p, float2 v) {
    asm volatile("st.global.cs.v2.f32 [%0], {%1, %2};"
                 :: "l"(p), "f"(v.x), "f"(v.y) : "memory");
}

// ---------------------------------------------------------------------------
// Kernel 1 (fused preproc) — unchanged (R14/R16; at its DRAM floor).
// ---------------------------------------------------------------------------
constexpr int DQ_BLOCKS = (N_DIM * GROUPS) / 256;                    // 2048
constexpr int CV_BLOCKS = (int)(((size_t)M_DIM * K_DIM / 8) / 256);  // 16384

__global__ __launch_bounds__(256) void preproc(
    const int* __restrict__ qw, const float* __restrict__ lut4,
    const float* __restrict__ lut5, const float* __restrict__ zp,
    const float* __restrict__ x)
{
    if (blockIdx.x < DQ_BLOCKS) {
        __shared__ float L[2][32];
        const int tid = threadIdx.x;
        const int idx = blockIdx.x * 256 + tid;
        const int g = idx & (GROUPS - 1);
        const int o = idx >> 7;

        float z = zp[0];
        float r = 2.0f - 3.0f / (1.0f + expf(-z));   // 2 - 3*sigmoid(z)
        float s = 1.0f - r;

        if (tid < 64) {
            int row = tid >> 5, c5 = tid & 31;
            int oo = blockIdx.x * 2 + row;
            L[row][c5] = r * lut4[oo * 16 + (c5 >> 1)] + s * lut5[oo * 32 + c5];
        }

        int base = o * GROUPS + g;
        unsigned q0 = (unsigned)qw[base];
        unsigned q1 = (unsigned)qw[base + PLANE_STRIDE];
        unsigned q2 = (unsigned)qw[base + 2 * PLANE_STRIDE];
        unsigned q3 = (unsigned)qw[base + 3 * PLANE_STRIDE];
        unsigned q4 = (unsigned)qw[base + 4 * PLANE_STRIDE];

        __syncthreads();
        const float* Lr = L[tid >> 7];

        __align__(16) __half vals[32];
#pragma unroll
        for (int b = 0; b < 32; b++) {
            unsigned c5 = (((q0 >> b) & 1u) << 4) | (((q1 >> b) & 1u) << 3)
                        | (((q2 >> b) & 1u) << 2) | (((q3 >> b) & 1u) << 1)
                        |  ((q4 >> b) & 1u);
            vals[b] = __float2half_rn(Lr[c5]);
        }
        __half* dst = g_wh + (size_t)o * K_DIM + g * 32;
        const uint4* sv = reinterpret_cast<const uint4*>(vals);
#pragma unroll
        for (int i = 0; i < 4; i++)
            reinterpret_cast<uint4*>(dst)[i] = sv[i];
    } else {
        size_t i = ((size_t)(blockIdx.x - DQ_BLOCKS) * 256 + threadIdx.x) * 8;
        float4 a = *reinterpret_cast<const float4*>(x + i);
        float4 b = *reinterpret_cast<const float4*>(x + i + 4);
        __align__(16) __half h[8];
        h[0] = __float2half_rn(a.x); h[1] = __float2half_rn(a.y);
        h[2] = __float2half_rn(a.z); h[3] = __float2half_rn(a.w);
        h[4] = __float2half_rn(b.x); h[5] = __float2half_rn(b.y);
        h[6] = __float2half_rn(b.z); h[7] = __float2half_rn(b.w);
        *reinterpret_cast<uint4*>(g_xh + i) = *reinterpret_cast<const uint4*>(h);
    }
}

// ---------------------------------------------------------------------------
// Kernel 2: persistent fp16 mma.sync GEMM.  out = xh @ wh^T + bias
// Grid = 148 (one CTA per SM); each CTA walks tiles t, t+148, ...
// At the LAST chunk of a tile it prefetches chunk 0 of its NEXT tile into
// the free stage, eliminating per-tile cold prologues and wave transitions.
// Inner loop identical to the R14/R16 optimum (rate-ceiling bound).
// ---------------------------------------------------------------------------
constexpr int BM = 256, BN = 128, BK = 128;
constexpr int PITCH = 136;                       // halves per smem row
constexpr int ROWS = BM + BN;                    // 384
constexpr int STAGE_HALVES = ROWS * PITCH;       // 52224
constexpr int NCHUNK = K_DIM / BK;               // 32
constexpr int SMEM_BYTES = 2 * STAGE_HALVES * 2; // 208896
constexpr int TILES_X = N_DIM / BN;              // 32
constexpr int TILES_Y = M_DIM / BM;              // 32
constexpr int NTILES = TILES_X * TILES_Y;        // 1024
constexpr int GEMM_GRID = 148;

__global__ __launch_bounds__(256, 1) void gemm_f16(
    const float* __restrict__ bias, float* __restrict__ out)
{
    extern __shared__ __half sm[];
    const int tid = threadIdx.x;
    const int lane = tid & 31, wid = tid >> 5;
    const int wm = wid >> 1, wn = wid & 1;       // warp grid 4x2
    const int grp = lane >> 2, qid = lane & 3;
    const uint32_t smAddr = smem_to_u32(sm);

    const int rbase = tid >> 4;
    const int seg = tid & 15;
    const uint32_t dst0 = (uint32_t)((rbase * PITCH + seg * 8) * 2);
    constexpr size_t SRC_IT = (size_t)16 * K_DIM * 2;
    constexpr uint32_t DST_IT = 16 * PITCH * 2;

    // per-tile source pointers (this thread's cp.async lanes)
    auto tile_ptrs = [&](int t, const char*& sA, const char*& sB) {
        int nx = t & (TILES_X - 1);
        int my = t >> 5;                         // t / TILES_X
        sA = (const char*)(g_xh + (size_t)(my * BM + rbase) * K_DIM + seg * 8);
        sB = (const char*)(g_wh + (size_t)(nx * BN + rbase) * K_DIM + seg * 8);
    };

    auto load_chunk = [&](const char* sA, const char* sB, int c, int stage) {
        uint32_t stAddr = smAddr + (uint32_t)(stage * STAGE_HALVES * 2) + dst0;
        size_t goff = (size_t)c * (BK * 2);
        const char* pA = sA + goff;
        const char* pB = sB + goff;
#pragma unroll
        for (int it = 0; it < 16; it++)          // A rows 0..255
            CP_ASYNC16(stAddr + it * DST_IT, pA + it * SRC_IT);
        uint32_t stB = stAddr + 16 * DST_IT;
#pragma unroll
        for (int it = 0; it < 8; it++)           // B rows 256..383
            CP_ASYNC16(stB + it * DST_IT, pB + it * SRC_IT);
    };

    int t = blockIdx.x;
    const char *cA, *cB, *nA = nullptr, *nB = nullptr;
    tile_ptrs(t, cA, cB);
    int stage = 0;
    load_chunk(cA, cB, 0, 0); CP_COMMIT();

    float acc[4][8][4];

    while (true) {
#pragma unroll
        for (int i = 0; i < 4; i++)
#pragma unroll
            for (int j = 0; j < 8; j++)
#pragma unroll
                for (int v = 0; v < 4; v++) acc[i][j][v] = 0.0f;

        const int tNext = t + GEMM_GRID;

        for (int c = 0; c < NCHUNK; c++) {
            CP_WAIT0();
            __syncthreads();

            if (c + 1 < NCHUNK) {
                load_chunk(cA, cB, c + 1, stage ^ 1); CP_COMMIT();
            } else if (tNext < NTILES) {
                tile_ptrs(tNext, nA, nB);
                load_chunk(nA, nB, 0, stage ^ 1); CP_COMMIT();
            }

            const __half* st = sm + stage * STAGE_HALVES;
#pragma unroll
            for (int ks = 0; ks < 8; ks++) {
                const int k0 = ks * 16;
                uint32_t a[4][4], b[8][2];
#pragma unroll
                for (int mt = 0; mt < 4; mt++) {
                    int m = wm * 64 + mt * 16 + grp;
                    const __half* p = st + m * PITCH + k0 + 2 * qid;
                    a[mt][0] = *reinterpret_cast<const uint32_t*>(p);
                    a[mt][1] = *reinterpret_cast<const uint32_t*>(p + 8 * PITCH);
                    a[mt][2] = *reinterpret_cast<const uint32_t*>(p + 8);
                    a[mt][3] = *reinterpret_cast<const uint32_t*>(p + 8 * PITCH + 8);
                }
#pragma unroll
                for (int nt = 0; nt < 8; nt++) {
                    int n = wn * 64 + nt * 8 + grp;
                    const __half* p = st + (BM + n) * PITCH + k0 + 2 * qid;
                    b[nt][0] = *reinterpret_cast<const uint32_t*>(p);
                    b[nt][1] = *reinterpret_cast<const uint32_t*>(p + 8);
                }
#pragma unroll
                for (int mt = 0; mt < 4; mt++)
#pragma unroll
                    for (int nt = 0; nt < 8; nt++)
                        mma_f16(acc[mt][nt], a[mt], b[nt]);
            }
            stage ^= 1;
        }

        // -- epilogue for tile t (overlaps next tile's chunk-0 cp.async) --
        {
            const int nx = t & (TILES_X - 1);
            const int my = t >> 5;
            const int mB = my * BM, nB0 = nx * BN;
#pragma unroll
            for (int mt = 0; mt < 4; mt++) {
                int m0 = mB + wm * 64 + mt * 16 + grp;
#pragma unroll
                for (int nt = 0; nt < 8; nt++) {
                    int n0 = nB0 + wn * 64 + nt * 8 + 2 * qid;
                    float2 bv = *reinterpret_cast<const float2*>(bias + n0);
                    stg_cs_f2(out + (size_t)m0 * N_DIM + n0,
                              make_float2(acc[mt][nt][0] + bv.x, acc[mt][nt][1] + bv.y));
                    stg_cs_f2(out + (size_t)(m0 + 8) * N_DIM + n0,
                              make_float2(acc[mt][nt][2] + bv.x, acc[mt][nt][3] + bv.y));
                }
            }
        }

        if (tNext >= NTILES) break;
        t = tNext;
        cA = nA; cB = nB;
    }
}

// ---------------------------------------------------------------------------
// Launch: inputs: x, z, lut4, lut5, bias, qweight
// ---------------------------------------------------------------------------
extern "C" void kernel_launch(void* const* d_in, const int* in_sizes, int n_in,
                              void* d_out, int out_size)
{
    const float* x    = (const float*)d_in[0];
    const float* z    = (const float*)d_in[1];
    const float* lut4 = (const float*)d_in[2];
    const float* lut5 = (const float*)d_in[3];
    const float* bias = (const float*)d_in[4];
    const int* qweight = (const int*)d_in[5];
    float* out = (float*)d_out;
    (void)in_sizes; (void)n_in; (void)out_size;

    cudaFuncSetAttribute(gemm_f16, cudaFuncAttributeMaxDynamicSharedMemorySize, SMEM_BYTES);

    preproc<<<DQ_BLOCKS + CV_BLOCKS, 256>>>(qweight, lut4, lut5, z, x);

    gemm_f16<<<GEMM_GRID, 256, SMEM_BYTES>>>(bias, out);
}